// round 14
// baseline (speedup 1.0000x reference)
#include <cuda_runtime.h>
#include <cstdint>
#include <math.h>

#define N_LEVELS 16
#define LOG2_T 19
#define TABLE_SIZE (1u << LOG2_T)
#define TABLE_MASK (TABLE_SIZE - 1u)

#define THREADS 256

struct ResParams { float resm1[N_LEVELS]; };

// R11 structure + 2 output elements per thread at offset half = total/2.
// half is a multiple of 8, so both elements share the same lane slot k,
// hence the same levels l0/l1, resolutions, and cache-policy predicate.
// All index math int32 (R10's long long overhead removed). Gathers: lane
// k==0 (levels 0,1; 117KB hot set) L1-cached __ldg, others L2-only __ldcg.
// Stores __stcs; warp stores remain 512B contiguous per instruction.
__global__ void __launch_bounds__(THREADS) hashgrid_kernel(
    const float* __restrict__ x,
    const float2* __restrict__ tables,
    float4* __restrict__ out,
    int half, ResParams rp)
{
    const int i0 = blockIdx.x * THREADS + threadIdx.x;
    if (i0 >= half) return;
    const int i1 = i0 + half;

    const int pA = i0 >> 3;
    const int pB = i1 >> 3;
    const int k  = i0 & 7;          // same for both elements (half % 8 == 0)

    // 8 lanes share each point's addresses -> L1 broadcast.
    const float pxA = __ldg(&x[3 * pA + 0]);
    const float pyA = __ldg(&x[3 * pA + 1]);
    const float pzA = __ldg(&x[3 * pA + 2]);
    const float pxB = __ldg(&x[3 * pB + 0]);
    const float pyB = __ldg(&x[3 * pB + 1]);
    const float pzB = __ldg(&x[3 * pB + 2]);

    // Match reference: x_norm = (x + 1) / 2 in f32 (no FMA contraction)
    const float xnA = __fmul_rn(__fadd_rn(pxA, 1.0f), 0.5f);
    const float ynA = __fmul_rn(__fadd_rn(pyA, 1.0f), 0.5f);
    const float znA = __fmul_rn(__fadd_rn(pzA, 1.0f), 0.5f);
    const float xnB = __fmul_rn(__fadd_rn(pxB, 1.0f), 0.5f);
    const float ynB = __fmul_rn(__fadd_rn(pyB, 1.0f), 0.5f);
    const float znB = __fmul_rn(__fadd_rn(pzB, 1.0f), 0.5f);

    const int l0 = 2 * k;
    const int l1 = 2 * k + 1;
    const float r0 = rp.resm1[l0];
    const float r1 = rp.resm1[l1];

    // scaled = x_norm * (res - 1); truncating cast == floor (operands >= 0)
    const uint32_t hA0 =
        (((uint32_t)__fmul_rn(xnA, r0)) ^
         (((uint32_t)__fmul_rn(ynA, r0)) * 2654435761u) ^
         (((uint32_t)__fmul_rn(znA, r0)) * 805459861u)) & TABLE_MASK;
    const uint32_t hA1 =
        (((uint32_t)__fmul_rn(xnA, r1)) ^
         (((uint32_t)__fmul_rn(ynA, r1)) * 2654435761u) ^
         (((uint32_t)__fmul_rn(znA, r1)) * 805459861u)) & TABLE_MASK;
    const uint32_t hB0 =
        (((uint32_t)__fmul_rn(xnB, r0)) ^
         (((uint32_t)__fmul_rn(ynB, r0)) * 2654435761u) ^
         (((uint32_t)__fmul_rn(znB, r0)) * 805459861u)) & TABLE_MASK;
    const uint32_t hB1 =
        (((uint32_t)__fmul_rn(xnB, r1)) ^
         (((uint32_t)__fmul_rn(ynB, r1)) * 2654435761u) ^
         (((uint32_t)__fmul_rn(znB, r1)) * 805459861u)) & TABLE_MASK;

    const float2* aA0 = &tables[(size_t)l0 * TABLE_SIZE + hA0];
    const float2* aA1 = &tables[(size_t)l1 * TABLE_SIZE + hA1];
    const float2* aB0 = &tables[(size_t)l0 * TABLE_SIZE + hB0];
    const float2* aB1 = &tables[(size_t)l1 * TABLE_SIZE + hB1];

    // 4 independent gathers in flight; uniform per-thread cache policy.
    const float2 fA0 = (k == 0) ? __ldg(aA0) : __ldcg(aA0);
    const float2 fA1 = (k == 0) ? __ldg(aA1) : __ldcg(aA1);
    const float2 fB0 = (k == 0) ? __ldg(aB0) : __ldcg(aB0);
    const float2 fB1 = (k == 0) ? __ldg(aB1) : __ldcg(aB1);

    // Evict-first stores: output is write-once, never re-read.
    __stcs(&out[(size_t)i0], make_float4(fA0.x, fA0.y, fA1.x, fA1.y));
    __stcs(&out[(size_t)i1], make_float4(fB0.x, fB0.y, fB1.x, fB1.y));
}

extern "C" void kernel_launch(void* const* d_in, const int* in_sizes, int n_in,
                              void* d_out, int out_size)
{
    const float*  x      = (const float*)d_in[0];
    const float2* tables = (const float2*)d_in[1];
    float4*       out    = (float4*)d_out;

    const int n = in_sizes[0] / 3;        // x has N*3 elements
    const int total = n * 8;              // output float4 count (2^24 here)
    const int half  = total / 2;          // multiple of 8 (n is even)

    // Resolutions via the same double-precision libm chain as the Python
    // reference: b = exp((log(2048) - log(16)) / 15); res_l = int(16 * b**l).
    // Proven bit-identical (rel_err == 0.0) across all passing rounds.
    ResParams rp;
    {
        const double b = exp((log(2048.0) - log(16.0)) / 15.0);
        for (int l = 0; l < N_LEVELS; l++) {
            int res = (int)(16.0 * pow(b, (double)l));
            rp.resm1[l] = (float)res - 1.0f;
        }
    }

    const int blocks = (half + THREADS - 1) / THREADS;
    hashgrid_kernel<<<blocks, THREADS>>>(x, tables, out, half, rp);
}

// round 15
// speedup vs baseline: 1.0121x; 1.0121x over previous
#include <cuda_runtime.h>
#include <cstdint>
#include <math.h>

#define N_LEVELS 16
#define LOG2_T 19
#define TABLE_SIZE (1u << LOG2_T)
#define TABLE_MASK (TABLE_SIZE - 1u)

#define THREADS 256

struct ResParams { float resm1[N_LEVELS]; };

// FINAL (R11, 156.0us, reproduced twice): 8 lanes per point, lane k handles
// levels 2k/2k+1, warp stores 512B contiguous (4 wavefronts = floor), __stcs
// streaming stores. Mixed gather cache policy — levels 0-1 (lane k==0; hot
// sets 32KB+85KB fit the 228KB L1) keep L1 allocation (__ldg); levels >=2
// bypass L1 (__ldcg) so their miss streams don't thrash the coarse set.
// Measured dead ends: smem transpose (R4), uniform __ldcg (R7), shuffle
// x-loads (R9), 2-elem ILP (R10/R14), level-2 L1 caching (R12). L1tex sits
// at its ~88% steady-state ceiling; ~36M wavefronts are irreducible.
__global__ void __launch_bounds__(THREADS) hashgrid_kernel(
    const float* __restrict__ x,
    const float2* __restrict__ tables,
    float4* __restrict__ out,
    int n, ResParams rp)
{
    const int tid = blockIdx.x * THREADS + threadIdx.x;
    const int p   = tid >> 3;       // point index
    const int k   = tid & 7;        // float4 slot within the output row
    if (p >= n) return;

    // 8 lanes share these addresses -> L1 broadcast, ~free.
    const float px = __ldg(&x[3 * p + 0]);
    const float py = __ldg(&x[3 * p + 1]);
    const float pz = __ldg(&x[3 * p + 2]);

    // Match reference: x_norm = (x + 1) / 2 in f32 (no FMA contraction)
    const float xn = __fmul_rn(__fadd_rn(px, 1.0f), 0.5f);
    const float yn = __fmul_rn(__fadd_rn(py, 1.0f), 0.5f);
    const float zn = __fmul_rn(__fadd_rn(pz, 1.0f), 0.5f);

    const int l0 = 2 * k;
    const int l1 = 2 * k + 1;

    const float r0 = rp.resm1[l0];
    const float r1 = rp.resm1[l1];

    // scaled = x_norm * (res - 1); truncating cast == floor (operands >= 0)
    const uint32_t gx0 = (uint32_t)__fmul_rn(xn, r0);
    const uint32_t gy0 = (uint32_t)__fmul_rn(yn, r0);
    const uint32_t gz0 = (uint32_t)__fmul_rn(zn, r0);
    const uint32_t gx1 = (uint32_t)__fmul_rn(xn, r1);
    const uint32_t gy1 = (uint32_t)__fmul_rn(yn, r1);
    const uint32_t gz1 = (uint32_t)__fmul_rn(zn, r1);

    const uint32_t h0 =
        (gx0 ^ (gy0 * 2654435761u) ^ (gz0 * 805459861u)) & TABLE_MASK;
    const uint32_t h1 =
        (gx1 ^ (gy1 * 2654435761u) ^ (gz1 * 805459861u)) & TABLE_MASK;

    const float2* a0 = &tables[(size_t)l0 * TABLE_SIZE + h0];
    const float2* a1 = &tables[(size_t)l1 * TABLE_SIZE + h1];

    // k is uniform per thread: levels 0-1 (k==0) L1-cached, rest L2-only.
    // Compiles to predicated LDGs; wavefront count unchanged.
    const float2 f0 = (k == 0) ? __ldg(a0) : __ldcg(a0);
    const float2 f1 = (k == 0) ? __ldg(a1) : __ldcg(a1);

    // Evict-first store: output is write-once, never re-read.
    __stcs(&out[(size_t)tid], make_float4(f0.x, f0.y, f1.x, f1.y));
}

extern "C" void kernel_launch(void* const* d_in, const int* in_sizes, int n_in,
                              void* d_out, int out_size)
{
    const float*  x      = (const float*)d_in[0];
    const float2* tables = (const float2*)d_in[1];
    float4*       out    = (float4*)d_out;

    const int n = in_sizes[0] / 3;  // x has N*3 elements

    // Resolutions via the same double-precision libm chain as the Python
    // reference: b = exp((log(2048) - log(16)) / 15); res_l = int(16 * b**l).
    // Proven bit-identical (rel_err == 0.0) across all passing rounds.
    ResParams rp;
    {
        const double b = exp((log(2048.0) - log(16.0)) / 15.0);
        for (int l = 0; l < N_LEVELS; l++) {
            int res = (int)(16.0 * pow(b, (double)l));
            rp.resm1[l] = (float)res - 1.0f;
        }
    }

    const long long total = (long long)n * 8;            // one thread per float4
    const int blocks = (int)((total + THREADS - 1) / THREADS);
    hashgrid_kernel<<<blocks, THREADS>>>(x, tables, out, n, rp);
}